// round 2
// baseline (speedup 1.0000x reference)
#include <cuda_runtime.h>
#include <math.h>

#define BB 8
#define NNODE 512
#define TT 64
#define NINP 64
#define NE 128
#define NH 128
#define RTOT (BB*NNODE)     /* 4096 */
#define G4 (4*NH)           /* 512  */
#define UVW (NE + G4)       /* 640  */
#define KC 16

// ---------------- scratch (allocation-free: __device__ globals) ----------------
__device__ float g_An[BB*NNODE*NNODE];   // 8.4 MB  normalized adjacency
__device__ float g_dinv[RTOT];
__device__ float g_h[RTOT*NH];
__device__ float g_c[RTOT*NH];
__device__ float g_uv[RTOT*UVW];         // [u | hW] = h @ Wcomb
__device__ float g_Hu[RTOT*NH];          // An @ u
__device__ float g_es[RTOT*NE];
__device__ float g_esW[RTOT*G4];         // step-invariant gate preactivation
__device__ float g_Xi[RTOT*NINP];
__device__ float g_Wcomb[NE*UVW];        // [Wpe | Whi|Whf|Whg|Who]
__device__ float g_WgH[NE*G4];           // bottom halves of Wii|Wif|Wig|Wio
__device__ float g_Wtop[NE*G4];          // top halves
__device__ float g_cvec[G4];             // b + bh + bpe@W_bot

__device__ __forceinline__ float sigm(float x) { return 1.f / (1.f + __expf(-x)); }

// ---------------- prep kernels ----------------
__global__ void prep_weights(
    const float* __restrict__ Wpe, const float* __restrict__ bpe,
    const float* __restrict__ Wii, const float* __restrict__ bii,
    const float* __restrict__ Whi, const float* __restrict__ bhi,
    const float* __restrict__ Wif, const float* __restrict__ bif_,
    const float* __restrict__ Whf, const float* __restrict__ bhf,
    const float* __restrict__ Wig, const float* __restrict__ big_,
    const float* __restrict__ Whg, const float* __restrict__ bhg,
    const float* __restrict__ Wio, const float* __restrict__ bio,
    const float* __restrict__ Who, const float* __restrict__ bho)
{
    int idx = blockIdx.x * blockDim.x + threadIdx.x;
    const float* Wg[4]  = {Wii, Wif, Wig, Wio};
    const float* Whx[4] = {Whi, Whf, Whg, Who};
    const float* bg[4]  = {bii, bif_, big_, bio};
    const float* bhx[4] = {bhi, bhf, bhg, bho};

    if (idx < NE*UVW) {                       // Wcomb
        int k = idx / UVW, j = idx % UVW;
        float v;
        if (j < NE) v = Wpe[k*NE + j];
        else { int j2 = j - NE; int g = j2 >> 7, o = j2 & 127; v = Whx[g][k*NH + o]; }
        g_Wcomb[idx] = v;
    }
    int i2 = idx - NE*UVW;
    if (i2 >= 0 && i2 < NE*G4) {              // WgH + Wtop
        int k = i2 / G4, go = i2 % G4; int g = go >> 7, o = go & 127;
        g_WgH[i2]  = Wg[g][(NE + k)*NH + o];
        g_Wtop[i2] = Wg[g][k*NH + o];
    }
    int i3 = i2 - NE*G4;
    if (i3 >= 0 && i3 < G4) {                 // cvec
        int g = i3 >> 7, o = i3 & 127;
        float s = bg[g][o] + bhx[g][o];
        for (int k = 0; k < NE; k++) s += bpe[k] * Wg[g][(NE + k)*NH + o];
        g_cvec[i3] = s;
    }
}

__global__ void prep_dinv(const float* __restrict__ A)
{
    int row = blockIdx.x;                     // b*512 + i
    const float* Ar = A + (size_t)row * NNODE;
    float s = 0.f;
    for (int j = threadIdx.x; j < NNODE; j += blockDim.x) s += Ar[j];
    __shared__ float red[4];
    for (int o = 16; o > 0; o >>= 1) s += __shfl_down_sync(0xffffffff, s, o);
    if ((threadIdx.x & 31) == 0) red[threadIdx.x >> 5] = s;
    __syncthreads();
    if (threadIdx.x == 0) {
        float d = red[0] + red[1] + red[2] + red[3];
        g_dinv[row] = d > 0.f ? rsqrtf(d) : 0.f;
    }
}

__global__ void prep_An(const float* __restrict__ A)
{
    int idx = blockIdx.x * blockDim.x + threadIdx.x;
    if (idx >= BB*NNODE*NNODE) return;
    int j  = idx & (NNODE - 1);
    int bi = idx >> 9;                        // b*512 + i
    int b  = idx >> 18;
    g_An[idx] = A[idx] * g_dinv[bi] * g_dinv[(b << 9) + j];
}

__global__ void prep_init(const float* __restrict__ X, float* __restrict__ out)
{
    int idx = blockIdx.x * blockDim.x + threadIdx.x;
    if (idx < RTOT*NH) { g_h[idx] = 0.f; g_c[idx] = 0.f; }
    if (idx < RTOT*NINP) {
        int r = idx >> 6, c = idx & 63;
        float v = X[(size_t)r * (TT*NINP) + c];   // X[b,n,0,c]
        g_Xi[idx] = v;
        out[(size_t)r * (TT*NINP) + c] = v;       // t = 0 slice
    }
}

__global__ void prep_es(const float* __restrict__ X,
                        const float* __restrict__ Wse, const float* __restrict__ bse)
{
    int r = blockIdx.x;
    __shared__ float xs[NINP];
    if (threadIdx.x < NINP) xs[threadIdx.x] = X[(size_t)r * (TT*NINP) + threadIdx.x];
    __syncthreads();
    int j = threadIdx.x;
    float s = bse[j];
    #pragma unroll 8
    for (int k = 0; k < NINP; k++) s += xs[k] * Wse[k*NE + j];
    g_es[r*NE + j] = s;
}

// ------------- generic batched SGEMM: C(M x N) = A(M x K) @ B(K x N) [+ bias] -------------
// grid: (M/32, N/128, batch). 256 threads, 4x4 micro-tile.
__global__ __launch_bounds__(256) void sgemm_t32(
    const float* __restrict__ A, int lda, long long strideA,
    const float* __restrict__ B, int ldb, long long strideB,
    float* __restrict__ C, int ldc, long long strideC,
    int K, const float* __restrict__ bias)
{
    const float* Ab = A + strideA * blockIdx.z + (size_t)blockIdx.x * 32 * lda;
    const float* Bb = B + strideB * blockIdx.z + (size_t)blockIdx.y * 128;
    float*       Cb = C + strideC * blockIdx.z + (size_t)blockIdx.x * 32 * ldc
                        + (size_t)blockIdx.y * 128;

    __shared__ float AsT[KC][36];   // [k][row], padded; 144B row stride keeps float4 alignment
    __shared__ float Bs[KC][128];

    int tid = threadIdx.x;
    int tx = tid & 31, ty = tid >> 5;
    int r0 = ty * 4, c0 = tx * 4;

    float acc[4][4];
    #pragma unroll
    for (int i = 0; i < 4; i++)
        #pragma unroll
        for (int j = 0; j < 4; j++) acc[i][j] = 0.f;

    for (int kk = 0; kk < K; kk += KC) {
        #pragma unroll
        for (int e = 0; e < 2; e++) {                 // A chunk: 32x16
            int el = 2*tid + e;
            int ar = el >> 4, ak = el & 15;
            AsT[ak][ar] = Ab[(size_t)ar * lda + kk + ak];
        }
        #pragma unroll
        for (int e = 0; e < 8; e++) {                 // B chunk: 16x128
            int el = tid + e * 256;
            int bk = el >> 7, bc = el & 127;
            Bs[bk][bc] = Bb[(size_t)(kk + bk) * ldb + bc];
        }
        __syncthreads();
        #pragma unroll
        for (int k = 0; k < KC; k++) {
            float4 av = *(const float4*)&AsT[k][r0];
            float4 bv = *(const float4*)&Bs[k][c0];
            float a[4] = {av.x, av.y, av.z, av.w};
            float b[4] = {bv.x, bv.y, bv.z, bv.w};
            #pragma unroll
            for (int i = 0; i < 4; i++)
                #pragma unroll
                for (int j = 0; j < 4; j++) acc[i][j] += a[i] * b[j];
        }
        __syncthreads();
    }
    #pragma unroll
    for (int i = 0; i < 4; i++) {
        float4 v = make_float4(acc[i][0], acc[i][1], acc[i][2], acc[i][3]);
        if (bias) {
            const float4 bv = *(const float4*)&bias[blockIdx.y*128 + c0];
            v.x += bv.x; v.y += bv.y; v.z += bv.z; v.w += bv.w;
        }
        *(float4*)&Cb[(size_t)(r0 + i) * ldc + c0] = v;
    }
}

// ------------- fused gates + LSTM update + output GEMM -------------
// One block = 32 rows. gates = esW + hW + Hu@WgH, passes ordered i,g,f,o so the
// elementwise LSTM state lives in registers; then out = Xi + h_t@Wout + bout,
// written to both Xi and the output time-slice t.
__global__ __launch_bounds__(256) void gates_kernel(
    float* __restrict__ out, const float* __restrict__ Wout,
    const float* __restrict__ bout, int t)
{
    __shared__ float HuT[NH][36];   // [k][row]; reused as h_t^T for the out-GEMM
    __shared__ float Bs[KC][128];

    int tid = threadIdx.x;
    int tx = tid & 31, ty = tid >> 5;
    int r0 = ty * 4, c0 = tx * 4;
    int rg = blockIdx.x * 32;

    #pragma unroll
    for (int e = 0; e < 16; e++) {                    // load Hu tile transposed
        int el = tid + e * 256;
        int r = el >> 7, k = el & 127;
        HuT[k][r] = g_Hu[(size_t)(rg + r) * NH + k];
    }
    __syncthreads();

    float rb[4][4];     // running elementwise buffer: i -> i*g -> tanh(c)
    float hval[4][4];
    const int order[4] = {0, 2, 1, 3};                // i, g, f, o

    #pragma unroll
    for (int p = 0; p < 4; p++) {
        int gb = order[p] * 128;
        float acc[4][4];
        #pragma unroll
        for (int i = 0; i < 4; i++) {
            float4 e4 = *(const float4*)&g_esW[(size_t)(rg + r0 + i) * G4 + gb + c0];
            float4 h4 = *(const float4*)&g_uv [(size_t)(rg + r0 + i) * UVW + NE + gb + c0];
            acc[i][0] = e4.x + h4.x; acc[i][1] = e4.y + h4.y;
            acc[i][2] = e4.z + h4.z; acc[i][3] = e4.w + h4.w;
        }
        for (int kk = 0; kk < NH; kk += KC) {
            #pragma unroll
            for (int e = 0; e < 8; e++) {
                int el = tid + e * 256;
                int k = el >> 7, c = el & 127;
                Bs[k][c] = g_WgH[(size_t)(kk + k) * G4 + gb + c];
            }
            __syncthreads();
            #pragma unroll
            for (int k = 0; k < KC; k++) {
                float4 av = *(const float4*)&HuT[kk + k][r0];
                float4 bv = *(const float4*)&Bs[k][c0];
                float a[4] = {av.x, av.y, av.z, av.w};
                float b[4] = {bv.x, bv.y, bv.z, bv.w};
                #pragma unroll
                for (int i = 0; i < 4; i++)
                    #pragma unroll
                    for (int j = 0; j < 4; j++) acc[i][j] += a[i] * b[j];
            }
            __syncthreads();
        }
        if (p == 0) {
            #pragma unroll
            for (int i = 0; i < 4; i++)
                #pragma unroll
                for (int j = 0; j < 4; j++) rb[i][j] = sigm(acc[i][j]);
        } else if (p == 1) {
            #pragma unroll
            for (int i = 0; i < 4; i++)
                #pragma unroll
                for (int j = 0; j < 4; j++) rb[i][j] *= tanhf(acc[i][j]);
        } else if (p == 2) {
            #pragma unroll
            for (int i = 0; i < 4; i++) {
                float4 co = *(const float4*)&g_c[(size_t)(rg + r0 + i) * NH + c0];
                float cold[4] = {co.x, co.y, co.z, co.w};
                float cn[4];
                #pragma unroll
                for (int j = 0; j < 4; j++) {
                    cn[j] = sigm(acc[i][j]) * cold[j] + rb[i][j];
                    rb[i][j] = tanhf(cn[j]);
                }
                *(float4*)&g_c[(size_t)(rg + r0 + i) * NH + c0] =
                    make_float4(cn[0], cn[1], cn[2], cn[3]);
            }
        } else {
            #pragma unroll
            for (int i = 0; i < 4; i++) {
                #pragma unroll
                for (int j = 0; j < 4; j++) hval[i][j] = sigm(acc[i][j]) * rb[i][j];
                *(float4*)&g_h[(size_t)(rg + r0 + i) * NH + c0] =
                    make_float4(hval[i][0], hval[i][1], hval[i][2], hval[i][3]);
            }
        }
    }

    __syncthreads();                                  // all passes done reading HuT
    #pragma unroll
    for (int i = 0; i < 4; i++)
        #pragma unroll
        for (int j = 0; j < 4; j++) HuT[c0 + j][r0 + i] = hval[i][j];  // h_t^T
    __syncthreads();

    // out(32x64) = Xi + h_t @ Wout + bout
    int oc0 = tx * 2;
    float oacc[4][2];
    #pragma unroll
    for (int i = 0; i < 4; i++) {
        float2 xv = *(const float2*)&g_Xi[(size_t)(rg + r0 + i) * NINP + oc0];
        float2 bv = *(const float2*)&bout[oc0];
        oacc[i][0] = xv.x + bv.x; oacc[i][1] = xv.y + bv.y;
    }
    for (int kk = 0; kk < NH; kk += KC) {
        #pragma unroll
        for (int e = 0; e < 4; e++) {
            int el = tid + e * 256;
            int k = el >> 6, c = el & 63;
            Bs[k][c] = Wout[(size_t)(kk + k) * NINP + c];
        }
        __syncthreads();
        #pragma unroll
        for (int k = 0; k < KC; k++) {
            float4 av = *(const float4*)&HuT[kk + k][r0];
            float a[4] = {av.x, av.y, av.z, av.w};
            float2 bv = *(const float2*)&Bs[k][oc0];
            #pragma unroll
            for (int i = 0; i < 4; i++) {
                oacc[i][0] += a[i] * bv.x;
                oacc[i][1] += a[i] * bv.y;
            }
        }
        __syncthreads();
    }
    #pragma unroll
    for (int i = 0; i < 4; i++) {
        size_t r = rg + r0 + i;
        float2 v = make_float2(oacc[i][0], oacc[i][1]);
        *(float2*)&g_Xi[r * NINP + oc0] = v;
        *(float2*)&out[r * (TT*NINP) + (size_t)t * NINP + oc0] = v;
    }
}

// ---------------- launch ----------------
extern "C" void kernel_launch(void* const* d_in, const int* in_sizes, int n_in,
                              void* d_out, int out_size)
{
    const float* X    = (const float*)d_in[0];
    const float* A    = (const float*)d_in[1];
    const float* Wse  = (const float*)d_in[2];
    const float* bse  = (const float*)d_in[3];
    const float* Wpe  = (const float*)d_in[4];
    const float* bpe  = (const float*)d_in[5];
    const float* Wii  = (const float*)d_in[6];
    const float* bii  = (const float*)d_in[7];
    const float* Whi  = (const float*)d_in[8];
    const float* bhi  = (const float*)d_in[9];
    const float* Wif  = (const float*)d_in[10];
    const float* bif_ = (const float*)d_in[11];
    const float* Whf  = (const float*)d_in[12];
    const float* bhf  = (const float*)d_in[13];
    const float* Wig  = (const float*)d_in[14];
    const float* big_ = (const float*)d_in[15];
    const float* Whg  = (const float*)d_in[16];
    const float* bhg  = (const float*)d_in[17];
    const float* Wio  = (const float*)d_in[18];
    const float* bio  = (const float*)d_in[19];
    const float* Who  = (const float*)d_in[20];
    const float* bho  = (const float*)d_in[21];
    const float* Wout = (const float*)d_in[22];
    const float* bout = (const float*)d_in[23];
    float* out = (float*)d_out;

    float *p_es, *p_esW, *p_uv, *p_h, *p_Hu, *p_An, *p_Wcomb, *p_Wtop, *p_cvec;
    cudaGetSymbolAddress((void**)&p_es,    g_es);
    cudaGetSymbolAddress((void**)&p_esW,   g_esW);
    cudaGetSymbolAddress((void**)&p_uv,    g_uv);
    cudaGetSymbolAddress((void**)&p_h,     g_h);
    cudaGetSymbolAddress((void**)&p_Hu,    g_Hu);
    cudaGetSymbolAddress((void**)&p_An,    g_An);
    cudaGetSymbolAddress((void**)&p_Wcomb, g_Wcomb);
    cudaGetSymbolAddress((void**)&p_Wtop,  g_Wtop);
    cudaGetSymbolAddress((void**)&p_cvec,  g_cvec);

    prep_weights<<<(NE*UVW + NE*G4 + G4 + 255)/256, 256>>>(
        Wpe, bpe, Wii, bii, Whi, bhi, Wif, bif_, Whf, bhf,
        Wig, big_, Whg, bhg, Wio, bio, Who, bho);
    prep_dinv<<<RTOT, 128>>>(A);
    prep_An<<<(BB*NNODE*NNODE + 255)/256, 256>>>(A);
    prep_init<<<(RTOT*NH + 255)/256, 256>>>(X, out);
    prep_es<<<RTOT, 128>>>(X, Wse, bse);

    // esW = es @ Wtop + cvec      (M=4096, K=128, N=512)
    sgemm_t32<<<dim3(RTOT/32, G4/128, 1), 256>>>(
        p_es, NE, 0, p_Wtop, G4, 0, p_esW, G4, 0, NE, p_cvec);

    for (int t = 1; t < TT; ++t) {
        // uv = h @ Wcomb           (M=4096, K=128, N=640)
        sgemm_t32<<<dim3(RTOT/32, UVW/128, 1), 256>>>(
            p_h, NH, 0, p_Wcomb, UVW, 0, p_uv, UVW, 0, NH, nullptr);
        // Hu = An @ u  (batched)   (M=512, K=512, N=128 per batch)
        sgemm_t32<<<dim3(NNODE/32, 1, BB), 256>>>(
            p_An, NNODE, (long long)NNODE*NNODE,
            p_uv, UVW,   (long long)NNODE*UVW,
            p_Hu, NH,    (long long)NNODE*NH,
            NNODE, nullptr);
        // gates + LSTM update + output
        gates_kernel<<<RTOT/32, 256>>>(out, Wout, bout, t);
    }
}